// round 4
// baseline (speedup 1.0000x reference)
#include <cuda_runtime.h>

#define Bc 2
#define Tc 2048
#define Cc 512
#define Hc 8
#define HDc 64
#define TOPKc 64
#define BHc (Bc*Hc)
#define Mr (Bc*Tc)
#define QT 16
#define KT 128

typedef unsigned long long ull;

// Scratch (device globals; allocations forbidden)
__device__ float g_Qh[BHc*Tc*HDc];
__device__ float g_Kh[BHc*Tc*HDc];
__device__ float g_Vh[BHc*Tc*HDc];
__device__ float g_Y [Bc*Tc*Cc];

// ---------------------------------------------------------------------------
// helpers
// ---------------------------------------------------------------------------
__device__ __forceinline__ unsigned f2u(float f) {
    unsigned b = __float_as_uint(f);
    return b ^ ((unsigned)((int)b >> 31) | 0x80000000u);
}
__device__ __forceinline__ float u2f(unsigned u) {
    unsigned b = (u & 0x80000000u) ? (u ^ 0x80000000u) : ~u;
    return __uint_as_float(b);
}
__device__ __forceinline__ ull packdup(float x) {
    ull d; asm("mov.b64 %0, {%1, %1};" : "=l"(d) : "f"(x)); return d;
}
__device__ __forceinline__ ull packpair(float x, float y) {
    ull d; asm("mov.b64 %0, {%1, %2};" : "=l"(d) : "f"(x), "f"(y)); return d;
}
__device__ __forceinline__ void fma2(ull& d, ull a, ull b, ull c) {
    asm("fma.rn.f32x2 %0, %1, %2, %3;" : "=l"(d) : "l"(a), "l"(b), "l"(c));
}
__device__ __forceinline__ float2 unpack2(ull v) {
    float x, y; asm("mov.b64 {%0, %1}, %2;" : "=f"(x), "=f"(y) : "l"(v));
    return make_float2(x, y);
}
__device__ __forceinline__ void cp16(void* dst_smem, const void* src) {
    unsigned sa = (unsigned)__cvta_generic_to_shared(dst_smem);
    asm volatile("cp.async.cg.shared.global [%0], [%1], 16;\n" :: "r"(sa), "l"(src));
}
#define CP_COMMIT() asm volatile("cp.async.commit_group;\n" ::: "memory")
#define CP_WAIT(N)  asm volatile("cp.async.wait_group %0;\n" :: "n"(N) : "memory")

// ---------------------------------------------------------------------------
// Fused QKV GEMM: 3 GEMMs over same A, grid.z selects weights/output.
// BM=BN=128, BK=8, 256 threads, f32x2 micro, double buffer.
// z==2 (V): fused row-norm per 64-dim head in epilogue.
// All outputs scattered head-major (b,h,t,d).
// ---------------------------------------------------------------------------
__global__ void __launch_bounds__(256, 2)
qkv_kernel(const float* __restrict__ A,
           const float* __restrict__ Wq, const float* __restrict__ bq,
           const float* __restrict__ Wk, const float* __restrict__ bk,
           const float* __restrict__ Wv, const float* __restrict__ bv,
           float* __restrict__ Qh, float* __restrict__ Kh, float* __restrict__ Vh)
{
    int z = blockIdx.z;
    const float* W    = (z == 0) ? Wq : (z == 1) ? Wk : Wv;
    const float* bias = (z == 0) ? bq : (z == 1) ? bk : bv;
    float* out        = (z == 0) ? Qh : (z == 1) ? Kh : Vh;

    __shared__ float As[2][8][128];
    __shared__ float Bs[2][8][128];

    int tid = threadIdx.x;
    int bm = blockIdx.y * 128;
    int bn = blockIdx.x * 128;
    int ty = tid >> 4;            // 0..15
    int tx = tid & 15;            // 0..15

    int arow = tid >> 1;          // 0..127
    int akq  = (tid & 1) * 4;     // 0 or 4
    int brow = tid >> 5;          // 0..7
    int bcol = (tid & 31) * 4;    // 0..124

    const float* Ag = A + (size_t)(bm + arow) * Cc + akq;
    const float* Wg = W + (size_t)brow * Cc + bn + bcol;

    ull acc[8][4];
    #pragma unroll
    for (int i = 0; i < 8; i++)
        #pragma unroll
        for (int j = 0; j < 4; j++) acc[i][j] = 0ULL;

    {
        float4 av = *reinterpret_cast<const float4*>(Ag);
        float4 bv4 = *reinterpret_cast<const float4*>(Wg);
        As[0][akq + 0][arow] = av.x;
        As[0][akq + 1][arow] = av.y;
        As[0][akq + 2][arow] = av.z;
        As[0][akq + 3][arow] = av.w;
        *reinterpret_cast<float4*>(&Bs[0][brow][bcol]) = bv4;
    }
    __syncthreads();

    #pragma unroll 1
    for (int kb = 0; kb < 64; kb++) {
        int cur = kb & 1;
        float4 an, bnv;
        if (kb < 63) {
            an  = *reinterpret_cast<const float4*>(Ag + (kb + 1) * 8);
            bnv = *reinterpret_cast<const float4*>(Wg + (size_t)(kb + 1) * 8 * Cc);
        }
        #pragma unroll
        for (int k = 0; k < 8; k++) {
            float4 a0 = *reinterpret_cast<const float4*>(&As[cur][k][ty * 4]);
            float4 a1 = *reinterpret_cast<const float4*>(&As[cur][k][64 + ty * 4]);
            float4 b0 = *reinterpret_cast<const float4*>(&Bs[cur][k][tx * 4]);
            float4 b1 = *reinterpret_cast<const float4*>(&Bs[cur][k][64 + tx * 4]);
            ull bb[4] = { packpair(b0.x, b0.y), packpair(b0.z, b0.w),
                          packpair(b1.x, b1.y), packpair(b1.z, b1.w) };
            ull aa[8] = { packdup(a0.x), packdup(a0.y), packdup(a0.z), packdup(a0.w),
                          packdup(a1.x), packdup(a1.y), packdup(a1.z), packdup(a1.w) };
            #pragma unroll
            for (int i = 0; i < 8; i++)
                #pragma unroll
                for (int j = 0; j < 4; j++)
                    fma2(acc[i][j], aa[i], bb[j], acc[i][j]);
        }
        if (kb < 63) {
            int nxt = cur ^ 1;
            As[nxt][akq + 0][arow] = an.x;
            As[nxt][akq + 1][arow] = an.y;
            As[nxt][akq + 2][arow] = an.z;
            As[nxt][akq + 3][arow] = an.w;
            *reinterpret_cast<float4*>(&Bs[nxt][brow][bcol]) = bnv;
            __syncthreads();
        }
    }

    float4 bia0 = *reinterpret_cast<const float4*>(bias + bn + tx * 4);
    float4 bia1 = *reinterpret_cast<const float4*>(bias + bn + 64 + tx * 4);
    #pragma unroll
    for (int i = 0; i < 8; i++) {
        int r = (i < 4) ? (ty * 4 + i) : (64 + ty * 4 + (i - 4));
        int mrow = bm + r;
        int b = mrow >> 11;
        int t = mrow & (Tc - 1);
        float2 c0 = unpack2(acc[i][0]);
        float2 c1 = unpack2(acc[i][1]);
        float2 c2 = unpack2(acc[i][2]);
        float2 c3 = unpack2(acc[i][3]);
        float4 o0 = make_float4(c0.x + bia0.x, c0.y + bia0.y, c1.x + bia0.z, c1.y + bia0.w);
        float4 o1 = make_float4(c2.x + bia1.x, c2.y + bia1.y, c3.x + bia1.z, c3.y + bia1.w);
        if (z == 2) {
            // fused v-norm: head even = o0 across the 16 tx lanes (half-warp),
            // head odd = o1. xor-shuffle offsets 1,2,4,8 stay within half-warp.
            float ss0 = o0.x*o0.x + o0.y*o0.y + o0.z*o0.z + o0.w*o0.w;
            float ss1 = o1.x*o1.x + o1.y*o1.y + o1.z*o1.z + o1.w*o1.w;
            #pragma unroll
            for (int off = 8; off; off >>= 1) {
                ss0 += __shfl_xor_sync(0xffffffffu, ss0, off);
                ss1 += __shfl_xor_sync(0xffffffffu, ss1, off);
            }
            float sc0 = 1.0f / fmaxf(sqrtf(ss0), 1e-12f);
            float sc1 = 1.0f / fmaxf(sqrtf(ss1), 1e-12f);
            o0.x *= sc0; o0.y *= sc0; o0.z *= sc0; o0.w *= sc0;
            o1.x *= sc1; o1.y *= sc1; o1.z *= sc1; o1.w *= sc1;
        }
        int n0 = bn + tx * 4;       int h0 = n0 >> 6, d0 = n0 & 63;
        int n1 = bn + 64 + tx * 4;  int h1 = n1 >> 6, d1 = n1 & 63;
        *reinterpret_cast<float4*>(out + ((size_t)((b * Hc + h0) * Tc + t) << 6) + d0) = o0;
        *reinterpret_cast<float4*>(out + ((size_t)((b * Hc + h1) * Tc + t) << 6) + d1) = o1;
    }
}

// ---------------------------------------------------------------------------
// Output projection GEMM (row-major out).
// ---------------------------------------------------------------------------
__global__ void __launch_bounds__(256, 2)
sgemm_kernel(const float* __restrict__ A, const float* __restrict__ W,
             const float* __restrict__ bias, float* __restrict__ out)
{
    __shared__ float As[2][8][128];
    __shared__ float Bs[2][8][128];

    int tid = threadIdx.x;
    int bm = blockIdx.y * 128;
    int bn = blockIdx.x * 128;
    int ty = tid >> 4;
    int tx = tid & 15;

    int arow = tid >> 1;
    int akq  = (tid & 1) * 4;
    int brow = tid >> 5;
    int bcol = (tid & 31) * 4;

    const float* Ag = A + (size_t)(bm + arow) * Cc + akq;
    const float* Wg = W + (size_t)brow * Cc + bn + bcol;

    ull acc[8][4];
    #pragma unroll
    for (int i = 0; i < 8; i++)
        #pragma unroll
        for (int j = 0; j < 4; j++) acc[i][j] = 0ULL;

    {
        float4 av = *reinterpret_cast<const float4*>(Ag);
        float4 bv4 = *reinterpret_cast<const float4*>(Wg);
        As[0][akq + 0][arow] = av.x;
        As[0][akq + 1][arow] = av.y;
        As[0][akq + 2][arow] = av.z;
        As[0][akq + 3][arow] = av.w;
        *reinterpret_cast<float4*>(&Bs[0][brow][bcol]) = bv4;
    }
    __syncthreads();

    #pragma unroll 1
    for (int kb = 0; kb < 64; kb++) {
        int cur = kb & 1;
        float4 an, bnv;
        if (kb < 63) {
            an  = *reinterpret_cast<const float4*>(Ag + (kb + 1) * 8);
            bnv = *reinterpret_cast<const float4*>(Wg + (size_t)(kb + 1) * 8 * Cc);
        }
        #pragma unroll
        for (int k = 0; k < 8; k++) {
            float4 a0 = *reinterpret_cast<const float4*>(&As[cur][k][ty * 4]);
            float4 a1 = *reinterpret_cast<const float4*>(&As[cur][k][64 + ty * 4]);
            float4 b0 = *reinterpret_cast<const float4*>(&Bs[cur][k][tx * 4]);
            float4 b1 = *reinterpret_cast<const float4*>(&Bs[cur][k][64 + tx * 4]);
            ull bb[4] = { packpair(b0.x, b0.y), packpair(b0.z, b0.w),
                          packpair(b1.x, b1.y), packpair(b1.z, b1.w) };
            ull aa[8] = { packdup(a0.x), packdup(a0.y), packdup(a0.z), packdup(a0.w),
                          packdup(a1.x), packdup(a1.y), packdup(a1.z), packdup(a1.w) };
            #pragma unroll
            for (int i = 0; i < 8; i++)
                #pragma unroll
                for (int j = 0; j < 4; j++)
                    fma2(acc[i][j], aa[i], bb[j], acc[i][j]);
        }
        if (kb < 63) {
            int nxt = cur ^ 1;
            As[nxt][akq + 0][arow] = an.x;
            As[nxt][akq + 1][arow] = an.y;
            As[nxt][akq + 2][arow] = an.z;
            As[nxt][akq + 3][arow] = an.w;
            *reinterpret_cast<float4*>(&Bs[nxt][brow][bcol]) = bnv;
            __syncthreads();
        }
    }

    float4 bia0 = *reinterpret_cast<const float4*>(bias + bn + tx * 4);
    float4 bia1 = *reinterpret_cast<const float4*>(bias + bn + 64 + tx * 4);
    #pragma unroll
    for (int i = 0; i < 8; i++) {
        int r = (i < 4) ? (ty * 4 + i) : (64 + ty * 4 + (i - 4));
        int mrow = bm + r;
        float2 c0 = unpack2(acc[i][0]);
        float2 c1 = unpack2(acc[i][1]);
        float2 c2 = unpack2(acc[i][2]);
        float2 c3 = unpack2(acc[i][3]);
        float4 o0 = make_float4(c0.x + bia0.x, c0.y + bia0.y, c1.x + bia0.z, c1.y + bia0.w);
        float4 o1 = make_float4(c2.x + bia1.x, c2.y + bia1.y, c3.x + bia1.z, c3.y + bia1.w);
        *reinterpret_cast<float4*>(out + (size_t)mrow * Cc + bn + tx * 4) = o0;
        *reinterpret_cast<float4*>(out + (size_t)mrow * Cc + bn + 64 + tx * 4) = o1;
    }
}

// ---------------------------------------------------------------------------
// Attention: QT=16 rows/block, 8 warps, W=2 rows per warp.
// cp.async double-buffered K tiles; f32x2 dots (packed over reduction dim);
// match_any-based exact byte-radix select (no atomics); sparse PV.
// ---------------------------------------------------------------------------
struct AttnSmem {
    float qs[QT][HDc];                 // 4 KB
    float kt[2][KT][68];               // 68 KB (pad 68: conflict-free 8-lane phases)
    unsigned su[QT][Tc];               // 128 KB scores / probs
    union RowSel {
        int hist[256];
        unsigned short sidx[512];
    } sel[QT];                         // 16 KB
};

__global__ void __launch_bounds__(256, 1)
attn_kernel(const float* __restrict__ Q, const float* __restrict__ K,
            const float* __restrict__ V, float* __restrict__ Y)
{
    extern __shared__ unsigned char raw[];
    AttnSmem* S = reinterpret_cast<AttnSmem*>(raw);

    int tid  = threadIdx.x;
    int warp = tid >> 5;
    int lane = tid & 31;

    int bh = blockIdx.y;
    int qbase = ((int)gridDim.x - 1 - (int)blockIdx.x) * QT;  // long rows first
    int n_max = qbase + QT;
    int qi0 = qbase + 2 * warp;
    int qi1 = qi0 + 1;

    const float* Kb = K + (size_t)bh * Tc * HDc;
    const float* Vb = V + (size_t)bh * Tc * HDc;

    // load 16 q rows (256 float4, one per thread)
    {
        int r = tid >> 4, i = tid & 15;
        reinterpret_cast<float4*>(S->qs[r])[i] =
            reinterpret_cast<const float4*>(Q + ((size_t)bh * Tc + qbase + r) * HDc)[i];
    }

    int ntiles = (n_max + KT - 1) / KT;

    // prologue: tile 0 via cp.async
    {
        #pragma unroll
        for (int i = 0; i < 8; i++) {
            int idx = tid + 256 * i;
            int kk = idx >> 4, dq = (idx & 15) * 4;
            cp16(&S->kt[0][kk][dq], Kb + (size_t)kk * HDc + dq);
        }
        CP_COMMIT();
    }

    #pragma unroll 1
    for (int t = 0; t < ntiles; t++) {
        int buf = t & 1;
        if (t + 1 < ntiles) {
            int t0n = (t + 1) * KT;
            #pragma unroll
            for (int i = 0; i < 8; i++) {
                int idx = tid + 256 * i;
                int kk = idx >> 4, dq = (idx & 15) * 4;
                cp16(&S->kt[buf ^ 1][kk][dq], Kb + (size_t)(t0n + kk) * HDc + dq);
            }
            CP_COMMIT();
            CP_WAIT(1);
        } else {
            CP_WAIT(0);
        }
        __syncthreads();

        // dot products: lane owns keys lane+32j; f32x2 packed over dims
        const ulonglong2* q2a = reinterpret_cast<const ulonglong2*>(S->qs[2 * warp]);
        const ulonglong2* q2b = reinterpret_cast<const ulonglong2*>(S->qs[2 * warp + 1]);
        ull acc0[4] = {0,0,0,0}, acc1[4] = {0,0,0,0};
        #pragma unroll
        for (int i = 0; i < 16; i++) {
            ulonglong2 qa = q2a[i];
            ulonglong2 qb = q2b[i];
            #pragma unroll
            for (int j = 0; j < 4; j++) {
                ulonglong2 kv = *reinterpret_cast<const ulonglong2*>(&S->kt[buf][lane + 32 * j][i * 4]);
                fma2(acc0[j], qa.x, kv.x, acc0[j]);
                fma2(acc0[j], qa.y, kv.y, acc0[j]);
                fma2(acc1[j], qb.x, kv.x, acc1[j]);
                fma2(acc1[j], qb.y, kv.y, acc1[j]);
            }
        }
        int t0 = t * KT;
        #pragma unroll
        for (int j = 0; j < 4; j++) {
            int k = t0 + lane + 32 * j;
            float2 s0 = unpack2(acc0[j]);
            float2 s1 = unpack2(acc1[j]);
            if (k <= qi0) S->su[2 * warp][k]     = f2u((s0.x + s0.y) * 0.125f);
            if (k <= qi1) S->su[2 * warp + 1][k] = f2u((s1.x + s1.y) * 0.125f);
        }
        __syncthreads();
    }

    // ---- per-row (warp-local) selection + softmax + PV
    #pragma unroll 1
    for (int rr = 0; rr < 2; rr++) {
        int row = 2 * warp + rr;
        int qi = qbase + row;
        int n = qi + 1;
        unsigned* su = S->su[row];
        volatile int* hist = S->sel[row].hist;

        unsigned thrU = 0u;
        if (n > TOPKc) {
            unsigned pref = 0u; int need = TOPKc;
            #pragma unroll 1
            for (int by = 3; by >= 0; --by) {
                int sh = by * 8;
                #pragma unroll
                for (int b = lane; b < 256; b += 32) hist[b] = 0;
                __syncwarp();
                unsigned hp = (by < 3) ? (pref >> (sh + 8)) : 0u;
                #pragma unroll 1
                for (int k0 = 0; k0 < n; k0 += 32) {
                    int k = k0 + lane;
                    bool valid = k < n;
                    unsigned u = valid ? su[k] : 0u;
                    bool sel = valid && (by == 3 || (u >> (sh + 8)) == hp);
                    unsigned byte = (u >> sh) & 255u;
                    unsigned pm = __ballot_sync(0xffffffffu, sel);
                    unsigned mm = __match_any_sync(0xffffffffu, byte) & pm;
                    if (sel && lane == (__ffs(mm) - 1))
                        hist[byte] += __popc(mm);
                }
                __syncwarp();
                int s = 0;
                #pragma unroll
                for (int j = 0; j < 8; j++) s += hist[255 - lane * 8 - j];
                int cum = s;
                #pragma unroll
                for (int off = 1; off < 32; off <<= 1) {
                    int v = __shfl_up_sync(0xffffffffu, cum, off);
                    if (lane >= off) cum += v;
                }
                unsigned bal = __ballot_sync(0xffffffffu, cum >= need);
                int selL = __ffs(bal) - 1;
                int above = __shfl_sync(0xffffffffu, cum - s, selL);
                int sneed = need - above;
                int res = 0;
                if (lane == selL) {
                    int c = 0;
                    #pragma unroll 1
                    for (int j = 0; j < 8; j++) {
                        int b = 255 - selL * 8 - j;
                        int h = hist[b];
                        if (c + h >= sneed) { res = (b << 16) | (sneed - c); break; }
                        c += h;
                    }
                }
                res = __shfl_sync(0xffffffffu, res, selL);
                pref |= (unsigned)(res >> 16) << sh;
                need = res & 0xffff;
            }
            thrU = pref;
        }
        __syncwarp();

        // ---- ballot compaction + row max
        unsigned short* sidx = S->sel[row].sidx;
        int m = 0; unsigned umax = 0u;
        #pragma unroll 1
        for (int k0 = 0; k0 < n; k0 += 32) {
            int k = k0 + lane;
            bool a = k < n;
            unsigned u = a ? su[k] : 0u;
            umax = max(umax, u);
            bool keep = a && (u >= thrU);
            unsigned bal = __ballot_sync(0xffffffffu, keep);
            if (keep) {
                int pos = m + __popc(bal & ((1u << lane) - 1u));
                if (pos < 512) sidx[pos] = (unsigned short)k;
            }
            m += __popc(bal);
        }
        if (m > 512) m = 512;
        #pragma unroll
        for (int off = 16; off; off >>= 1)
            umax = max(umax, __shfl_xor_sync(0xffffffffu, umax, off));

        // ---- softmax over survivors
        float maxf = u2f(umax);
        float lsum = 0.f;
        for (int j = lane; j < m; j += 32) {
            int k = sidx[j];
            float p = __expf(u2f(su[k]) - maxf);
            su[k] = __float_as_uint(p);
            lsum += p;
        }
        __syncwarp();
        #pragma unroll
        for (int off = 16; off; off >>= 1) lsum += __shfl_xor_sync(0xffffffffu, lsum, off);
        float rinv = 1.0f / lsum;

        // ---- sparse PV
        const float2* V2 = reinterpret_cast<const float2*>(Vb);
        float2 y = make_float2(0.f, 0.f);
        int j = 0;
        for (; j + 4 <= m; j += 4) {
            int k0 = sidx[j + 0], k1 = sidx[j + 1], k2 = sidx[j + 2], k3 = sidx[j + 3];
            float p0 = __uint_as_float(su[k0]);
            float p1 = __uint_as_float(su[k1]);
            float p2 = __uint_as_float(su[k2]);
            float p3 = __uint_as_float(su[k3]);
            float2 v0 = V2[(size_t)k0 * 32 + lane];
            float2 v1 = V2[(size_t)k1 * 32 + lane];
            float2 v2 = V2[(size_t)k2 * 32 + lane];
            float2 v3 = V2[(size_t)k3 * 32 + lane];
            y.x += p0 * v0.x + p1 * v1.x + p2 * v2.x + p3 * v3.x;
            y.y += p0 * v0.y + p1 * v1.y + p2 * v2.y + p3 * v3.y;
        }
        for (; j < m; j++) {
            int k = sidx[j];
            float p = __uint_as_float(su[k]);
            float2 v = V2[(size_t)k * 32 + lane];
            y.x += p * v.x; y.y += p * v.y;
        }
        int b = bh >> 3, h = bh & 7;
        *reinterpret_cast<float2*>(Y + (size_t)(b * Tc + qi) * Cc + h * HDc + lane * 2) =
            make_float2(y.x * rinv, y.y * rinv);
    }
}

// ---------------------------------------------------------------------------
extern "C" void kernel_launch(void* const* d_in, const int* in_sizes, int n_in,
                              void* d_out, int out_size)
{
    const float* q  = (const float*)d_in[0];
    const float* Wq = (const float*)d_in[2];
    const float* bq = (const float*)d_in[3];
    const float* Wk = (const float*)d_in[4];
    const float* bk = (const float*)d_in[5];
    const float* Wv = (const float*)d_in[6];
    const float* bv = (const float*)d_in[7];
    const float* Wp = (const float*)d_in[8];
    const float* bp = (const float*)d_in[9];

    float *Qh, *Kh, *Vh, *Yb;
    cudaGetSymbolAddress((void**)&Qh, g_Qh);
    cudaGetSymbolAddress((void**)&Kh, g_Kh);
    cudaGetSymbolAddress((void**)&Vh, g_Vh);
    cudaGetSymbolAddress((void**)&Yb, g_Y);

    cudaFuncSetAttribute(attn_kernel, cudaFuncAttributeMaxDynamicSharedMemorySize,
                         (int)sizeof(AttnSmem));

    qkv_kernel<<<dim3(Cc / 128, Mr / 128, 3), 256>>>(q, Wq, bq, Wk, bk, Wv, bv, Qh, Kh, Vh);
    attn_kernel<<<dim3(Tc / QT, BHc), 256, sizeof(AttnSmem)>>>(Qh, Kh, Vh, Yb);
    sgemm_kernel<<<dim3(Cc / 128, Mr / 128), 256>>>(Yb, Wp, bp, (float*)d_out);
}

// round 5
// speedup vs baseline: 1.2940x; 1.2940x over previous
#include <cuda_runtime.h>

#define Bc 2
#define Tc 2048
#define Cc 512
#define Hc 8
#define HDc 64
#define TOPKc 64
#define BHc (Bc*Hc)
#define Mr (Bc*Tc)
#define QT 8
#define KT 128

typedef unsigned long long ull;

// Scratch (device globals; allocations forbidden)
__device__ float g_Qh[BHc*Tc*HDc];
__device__ float g_Kh[BHc*Tc*HDc];
__device__ float g_Vh[BHc*Tc*HDc];
__device__ float g_Y [Bc*Tc*Cc];

// ---------------------------------------------------------------------------
// helpers
// ---------------------------------------------------------------------------
__device__ __forceinline__ unsigned f2u(float f) {
    unsigned b = __float_as_uint(f);
    return b ^ ((unsigned)((int)b >> 31) | 0x80000000u);
}
__device__ __forceinline__ float u2f(unsigned u) {
    unsigned b = (u & 0x80000000u) ? (u ^ 0x80000000u) : ~u;
    return __uint_as_float(b);
}
__device__ __forceinline__ ull packdup(float x) {
    ull d; asm("mov.b64 %0, {%1, %1};" : "=l"(d) : "f"(x)); return d;
}
__device__ __forceinline__ ull packpair(float x, float y) {
    ull d; asm("mov.b64 %0, {%1, %2};" : "=l"(d) : "f"(x), "f"(y)); return d;
}
__device__ __forceinline__ void fma2(ull& d, ull a, ull b, ull c) {
    asm("fma.rn.f32x2 %0, %1, %2, %3;" : "=l"(d) : "l"(a), "l"(b), "l"(c));
}
__device__ __forceinline__ float2 unpack2(ull v) {
    float x, y; asm("mov.b64 {%0, %1}, %2;" : "=f"(x), "=f"(y) : "l"(v));
    return make_float2(x, y);
}

// ---------------------------------------------------------------------------
// Fused QKV GEMM: grid.z selects weights/output. BM=BN=128, BK=8, 256 thr,
// f32x2 micro, double buffer. z==2 (V): fused per-head row-norm in epilogue.
// ---------------------------------------------------------------------------
__global__ void __launch_bounds__(256, 2)
qkv_kernel(const float* __restrict__ A,
           const float* __restrict__ Wq, const float* __restrict__ bq,
           const float* __restrict__ Wk, const float* __restrict__ bk,
           const float* __restrict__ Wv, const float* __restrict__ bv,
           float* __restrict__ Qh, float* __restrict__ Kh, float* __restrict__ Vh)
{
    int z = blockIdx.z;
    const float* W    = (z == 0) ? Wq : (z == 1) ? Wk : Wv;
    const float* bias = (z == 0) ? bq : (z == 1) ? bk : bv;
    float* out        = (z == 0) ? Qh : (z == 1) ? Kh : Vh;

    __shared__ float As[2][8][128];
    __shared__ float Bs[2][8][128];

    int tid = threadIdx.x;
    int bm = blockIdx.y * 128;
    int bn = blockIdx.x * 128;
    int ty = tid >> 4;
    int tx = tid & 15;

    int arow = tid >> 1;
    int akq  = (tid & 1) * 4;
    int brow = tid >> 5;
    int bcol = (tid & 31) * 4;

    const float* Ag = A + (size_t)(bm + arow) * Cc + akq;
    const float* Wg = W + (size_t)brow * Cc + bn + bcol;

    ull acc[8][4];
    #pragma unroll
    for (int i = 0; i < 8; i++)
        #pragma unroll
        for (int j = 0; j < 4; j++) acc[i][j] = 0ULL;

    {
        float4 av = *reinterpret_cast<const float4*>(Ag);
        float4 bv4 = *reinterpret_cast<const float4*>(Wg);
        As[0][akq + 0][arow] = av.x;
        As[0][akq + 1][arow] = av.y;
        As[0][akq + 2][arow] = av.z;
        As[0][akq + 3][arow] = av.w;
        *reinterpret_cast<float4*>(&Bs[0][brow][bcol]) = bv4;
    }
    __syncthreads();

    #pragma unroll 1
    for (int kb = 0; kb < 64; kb++) {
        int cur = kb & 1;
        float4 an, bnv;
        if (kb < 63) {
            an  = *reinterpret_cast<const float4*>(Ag + (kb + 1) * 8);
            bnv = *reinterpret_cast<const float4*>(Wg + (size_t)(kb + 1) * 8 * Cc);
        }
        #pragma unroll
        for (int k = 0; k < 8; k++) {
            float4 a0 = *reinterpret_cast<const float4*>(&As[cur][k][ty * 4]);
            float4 a1 = *reinterpret_cast<const float4*>(&As[cur][k][64 + ty * 4]);
            float4 b0 = *reinterpret_cast<const float4*>(&Bs[cur][k][tx * 4]);
            float4 b1 = *reinterpret_cast<const float4*>(&Bs[cur][k][64 + tx * 4]);
            ull bb[4] = { packpair(b0.x, b0.y), packpair(b0.z, b0.w),
                          packpair(b1.x, b1.y), packpair(b1.z, b1.w) };
            ull aa[8] = { packdup(a0.x), packdup(a0.y), packdup(a0.z), packdup(a0.w),
                          packdup(a1.x), packdup(a1.y), packdup(a1.z), packdup(a1.w) };
            #pragma unroll
            for (int i = 0; i < 8; i++)
                #pragma unroll
                for (int j = 0; j < 4; j++)
                    fma2(acc[i][j], aa[i], bb[j], acc[i][j]);
        }
        if (kb < 63) {
            int nxt = cur ^ 1;
            As[nxt][akq + 0][arow] = an.x;
            As[nxt][akq + 1][arow] = an.y;
            As[nxt][akq + 2][arow] = an.z;
            As[nxt][akq + 3][arow] = an.w;
            *reinterpret_cast<float4*>(&Bs[nxt][brow][bcol]) = bnv;
            __syncthreads();
        }
    }

    float4 bia0 = *reinterpret_cast<const float4*>(bias + bn + tx * 4);
    float4 bia1 = *reinterpret_cast<const float4*>(bias + bn + 64 + tx * 4);
    #pragma unroll
    for (int i = 0; i < 8; i++) {
        int r = (i < 4) ? (ty * 4 + i) : (64 + ty * 4 + (i - 4));
        int mrow = bm + r;
        int b = mrow >> 11;
        int t = mrow & (Tc - 1);
        float2 c0 = unpack2(acc[i][0]);
        float2 c1 = unpack2(acc[i][1]);
        float2 c2 = unpack2(acc[i][2]);
        float2 c3 = unpack2(acc[i][3]);
        float4 o0 = make_float4(c0.x + bia0.x, c0.y + bia0.y, c1.x + bia0.z, c1.y + bia0.w);
        float4 o1 = make_float4(c2.x + bia1.x, c2.y + bia1.y, c3.x + bia1.z, c3.y + bia1.w);
        if (z == 2) {
            float ss0 = o0.x*o0.x + o0.y*o0.y + o0.z*o0.z + o0.w*o0.w;
            float ss1 = o1.x*o1.x + o1.y*o1.y + o1.z*o1.z + o1.w*o1.w;
            #pragma unroll
            for (int off = 8; off; off >>= 1) {
                ss0 += __shfl_xor_sync(0xffffffffu, ss0, off);
                ss1 += __shfl_xor_sync(0xffffffffu, ss1, off);
            }
            float sc0 = 1.0f / fmaxf(sqrtf(ss0), 1e-12f);
            float sc1 = 1.0f / fmaxf(sqrtf(ss1), 1e-12f);
            o0.x *= sc0; o0.y *= sc0; o0.z *= sc0; o0.w *= sc0;
            o1.x *= sc1; o1.y *= sc1; o1.z *= sc1; o1.w *= sc1;
        }
        int n0 = bn + tx * 4;       int h0 = n0 >> 6, d0 = n0 & 63;
        int n1 = bn + 64 + tx * 4;  int h1 = n1 >> 6, d1 = n1 & 63;
        *reinterpret_cast<float4*>(out + ((size_t)((b * Hc + h0) * Tc + t) << 6) + d0) = o0;
        *reinterpret_cast<float4*>(out + ((size_t)((b * Hc + h1) * Tc + t) << 6) + d1) = o1;
    }
}

// ---------------------------------------------------------------------------
// Output projection GEMM (row-major out).
// ---------------------------------------------------------------------------
__global__ void __launch_bounds__(256, 2)
sgemm_kernel(const float* __restrict__ A, const float* __restrict__ W,
             const float* __restrict__ bias, float* __restrict__ out)
{
    __shared__ float As[2][8][128];
    __shared__ float Bs[2][8][128];

    int tid = threadIdx.x;
    int bm = blockIdx.y * 128;
    int bn = blockIdx.x * 128;
    int ty = tid >> 4;
    int tx = tid & 15;

    int arow = tid >> 1;
    int akq  = (tid & 1) * 4;
    int brow = tid >> 5;
    int bcol = (tid & 31) * 4;

    const float* Ag = A + (size_t)(bm + arow) * Cc + akq;
    const float* Wg = W + (size_t)brow * Cc + bn + bcol;

    ull acc[8][4];
    #pragma unroll
    for (int i = 0; i < 8; i++)
        #pragma unroll
        for (int j = 0; j < 4; j++) acc[i][j] = 0ULL;

    {
        float4 av = *reinterpret_cast<const float4*>(Ag);
        float4 bv4 = *reinterpret_cast<const float4*>(Wg);
        As[0][akq + 0][arow] = av.x;
        As[0][akq + 1][arow] = av.y;
        As[0][akq + 2][arow] = av.z;
        As[0][akq + 3][arow] = av.w;
        *reinterpret_cast<float4*>(&Bs[0][brow][bcol]) = bv4;
    }
    __syncthreads();

    #pragma unroll 1
    for (int kb = 0; kb < 64; kb++) {
        int cur = kb & 1;
        float4 an, bnv;
        if (kb < 63) {
            an  = *reinterpret_cast<const float4*>(Ag + (kb + 1) * 8);
            bnv = *reinterpret_cast<const float4*>(Wg + (size_t)(kb + 1) * 8 * Cc);
        }
        #pragma unroll
        for (int k = 0; k < 8; k++) {
            float4 a0 = *reinterpret_cast<const float4*>(&As[cur][k][ty * 4]);
            float4 a1 = *reinterpret_cast<const float4*>(&As[cur][k][64 + ty * 4]);
            float4 b0 = *reinterpret_cast<const float4*>(&Bs[cur][k][tx * 4]);
            float4 b1 = *reinterpret_cast<const float4*>(&Bs[cur][k][64 + tx * 4]);
            ull bb[4] = { packpair(b0.x, b0.y), packpair(b0.z, b0.w),
                          packpair(b1.x, b1.y), packpair(b1.z, b1.w) };
            ull aa[8] = { packdup(a0.x), packdup(a0.y), packdup(a0.z), packdup(a0.w),
                          packdup(a1.x), packdup(a1.y), packdup(a1.z), packdup(a1.w) };
            #pragma unroll
            for (int i = 0; i < 8; i++)
                #pragma unroll
                for (int j = 0; j < 4; j++)
                    fma2(acc[i][j], aa[i], bb[j], acc[i][j]);
        }
        if (kb < 63) {
            int nxt = cur ^ 1;
            As[nxt][akq + 0][arow] = an.x;
            As[nxt][akq + 1][arow] = an.y;
            As[nxt][akq + 2][arow] = an.z;
            As[nxt][akq + 3][arow] = an.w;
            *reinterpret_cast<float4*>(&Bs[nxt][brow][bcol]) = bnv;
            __syncthreads();
        }
    }

    float4 bia0 = *reinterpret_cast<const float4*>(bias + bn + tx * 4);
    float4 bia1 = *reinterpret_cast<const float4*>(bias + bn + 64 + tx * 4);
    #pragma unroll
    for (int i = 0; i < 8; i++) {
        int r = (i < 4) ? (ty * 4 + i) : (64 + ty * 4 + (i - 4));
        int mrow = bm + r;
        float2 c0 = unpack2(acc[i][0]);
        float2 c1 = unpack2(acc[i][1]);
        float2 c2 = unpack2(acc[i][2]);
        float2 c3 = unpack2(acc[i][3]);
        float4 o0 = make_float4(c0.x + bia0.x, c0.y + bia0.y, c1.x + bia0.z, c1.y + bia0.w);
        float4 o1 = make_float4(c2.x + bia1.x, c2.y + bia1.y, c3.x + bia1.z, c3.y + bia1.w);
        *reinterpret_cast<float4*>(out + (size_t)mrow * Cc + bn + tx * 4) = o0;
        *reinterpret_cast<float4*>(out + (size_t)mrow * Cc + bn + 64 + tx * 4) = o1;
    }
}

// ---------------------------------------------------------------------------
// Attention: QT=8 rows/block (2 blocks/SM), 8 warps.
// Score phase: warp w computes rows {2(w&3), 2(w&3)+1} over key-half (w>>2):
// every kv LDS feeds 2 rows, f32x2 over reduction dim. Next K tile prefetched
// into registers during compute (no extra SMEM).
// Select: warp-local exact byte-radix via match_any (no atomics), then ballot
// compaction, softmax over survivors, sparse PV.
// ---------------------------------------------------------------------------
struct AttnSmem {
    float qs[QT][HDc];                 // 2 KB
    float kt[KT][68];                  // 34.8 KB (pad 68 -> conflict-free LDS.128)
    unsigned su[QT][Tc];               // 64 KB scores / probs
    union RowSel {
        int hist[256];
        unsigned short sidx[512];
    } sel[QT];                         // 8 KB
};

__global__ void __launch_bounds__(256, 2)
attn_kernel(const float* __restrict__ Q, const float* __restrict__ K,
            const float* __restrict__ V, float* __restrict__ Y)
{
    extern __shared__ unsigned char raw[];
    AttnSmem* S = reinterpret_cast<AttnSmem*>(raw);

    int tid  = threadIdx.x;
    int warp = tid >> 5;
    int lane = tid & 31;

    int bh = blockIdx.y;
    int qbase = ((int)gridDim.x - 1 - (int)blockIdx.x) * QT;  // long rows first
    int n_max = qbase + QT;

    const float* Kb = K + (size_t)bh * Tc * HDc;
    const float* Vb = V + (size_t)bh * Tc * HDc;

    // load 8 q rows (128 float4)
    if (tid < 128) {
        int r = tid >> 4, i = tid & 15;
        reinterpret_cast<float4*>(S->qs[r])[i] =
            reinterpret_cast<const float4*>(Q + ((size_t)bh * Tc + qbase + r) * HDc)[i];
    }

    int ntiles = (n_max + KT - 1) / KT;

    // score-phase mapping: 2 rows x half the keys per warp
    int half  = warp >> 2;              // 0/1 -> key half
    int rpair = (warp & 3) * 2;         // row pair base
    int qiA = qbase + rpair;
    int qiB = qiA + 1;
    const ulonglong2* q2a = reinterpret_cast<const ulonglong2*>(S->qs[rpair]);
    const ulonglong2* q2b = reinterpret_cast<const ulonglong2*>(S->qs[rpair + 1]);

    int ldrow = tid >> 4;               // 0..15: row within tile chunk
    int lddq  = (tid & 15) * 4;         // dim offset

    // prologue: tile 0 -> registers
    float4 rv[8];
    #pragma unroll
    for (int i = 0; i < 8; i++)
        rv[i] = *reinterpret_cast<const float4*>(Kb + (size_t)(ldrow + 16 * i) * HDc + lddq);

    #pragma unroll 1
    for (int t = 0; t < ntiles; t++) {
        __syncthreads();   // previous tile's compute done; kt reusable
        #pragma unroll
        for (int i = 0; i < 8; i++)
            *reinterpret_cast<float4*>(&S->kt[ldrow + 16 * i][lddq]) = rv[i];
        __syncthreads();

        if (t + 1 < ntiles) {
            int t0n = (t + 1) * KT;
            #pragma unroll
            for (int i = 0; i < 8; i++)
                rv[i] = *reinterpret_cast<const float4*>(
                            Kb + (size_t)(t0n + ldrow + 16 * i) * HDc + lddq);
        }

        ull a0[2] = {0, 0}, a1[2] = {0, 0};
        #pragma unroll
        for (int i = 0; i < 16; i++) {
            ulonglong2 qa = q2a[i];
            ulonglong2 qb = q2b[i];
            #pragma unroll
            for (int j = 0; j < 2; j++) {
                ulonglong2 kv = *reinterpret_cast<const ulonglong2*>(
                    &S->kt[half * 64 + lane + 32 * j][i * 4]);
                fma2(a0[j], qa.x, kv.x, a0[j]);
                fma2(a0[j], qa.y, kv.y, a0[j]);
                fma2(a1[j], qb.x, kv.x, a1[j]);
                fma2(a1[j], qb.y, kv.y, a1[j]);
            }
        }
        int t0 = t * KT + half * 64;
        #pragma unroll
        for (int j = 0; j < 2; j++) {
            int k = t0 + lane + 32 * j;
            float2 s0 = unpack2(a0[j]);
            float2 s1 = unpack2(a1[j]);
            if (k <= qiA) S->su[rpair][k]     = f2u((s0.x + s0.y) * 0.125f);
            if (k <= qiB) S->su[rpair + 1][k] = f2u((s1.x + s1.y) * 0.125f);
        }
    }
    __syncthreads();   // all rows' scores visible; switch to warp<->row mapping

    int row = warp;
    int qi = qbase + row;
    int n = qi + 1;
    unsigned* su = S->su[row];
    int* hist = S->sel[row].hist;

    // ---- exact rank-64 threshold: 4-pass byte radix, match_any (no atomics)
    unsigned thrU = 0u;
    if (n > TOPKc) {
        unsigned pref = 0u; int need = TOPKc;
        #pragma unroll 1
        for (int by = 3; by >= 0; --by) {
            int sh = by * 8;
            #pragma unroll
            for (int b = lane; b < 256; b += 32) hist[b] = 0;
            __syncwarp();
            unsigned hp = (by < 3) ? (pref >> (sh + 8)) : 0u;
            #pragma unroll 1
            for (int k0 = 0; k0 < n; k0 += 32) {
                int k = k0 + lane;
                bool valid = k < n;
                unsigned u = valid ? su[k] : 0u;
                bool sel = valid && (by == 3 || (u >> (sh + 8)) == hp);
                unsigned byte = (u >> sh) & 255u;
                unsigned pm = __ballot_sync(0xffffffffu, sel);
                unsigned mm = __match_any_sync(0xffffffffu, byte) & pm;
                if (sel && lane == (__ffs(mm) - 1))
                    hist[byte] += __popc(mm);
            }
            __syncwarp();
            int s = 0;
            #pragma unroll
            for (int j = 0; j < 8; j++) s += hist[255 - lane * 8 - j];
            int cum = s;
            #pragma unroll
            for (int off = 1; off < 32; off <<= 1) {
                int v = __shfl_up_sync(0xffffffffu, cum, off);
                if (lane >= off) cum += v;
            }
            unsigned bal = __ballot_sync(0xffffffffu, cum >= need);
            int selL = __ffs(bal) - 1;
            int above = __shfl_sync(0xffffffffu, cum - s, selL);
            int sneed = need - above;
            int res = 0;
            if (lane == selL) {
                int c = 0;
                #pragma unroll 1
                for (int j = 0; j < 8; j++) {
                    int b = 255 - selL * 8 - j;
                    int h = hist[b];
                    if (c + h >= sneed) { res = (b << 16) | (sneed - c); break; }
                    c += h;
                }
            }
            res = __shfl_sync(0xffffffffu, res, selL);
            pref |= (unsigned)(res >> 16) << sh;
            need = res & 0xffff;
        }
        thrU = pref;
    }
    __syncwarp();

    // ---- ballot compaction (ordered) + row max
    unsigned short* sidx = S->sel[row].sidx;
    int m = 0; unsigned umax = 0u;
    #pragma unroll 1
    for (int k0 = 0; k0 < n; k0 += 32) {
        int k = k0 + lane;
        bool a = k < n;
        unsigned u = a ? su[k] : 0u;
        umax = max(umax, u);
        bool keep = a && (u >= thrU);
        unsigned bal = __ballot_sync(0xffffffffu, keep);
        if (keep) {
            int pos = m + __popc(bal & ((1u << lane) - 1u));
            if (pos < 512) sidx[pos] = (unsigned short)k;
        }
        m += __popc(bal);
    }
    if (m > 512) m = 512;
    #pragma unroll
    for (int off = 16; off; off >>= 1)
        umax = max(umax, __shfl_xor_sync(0xffffffffu, umax, off));

    // ---- softmax over survivors (probs overwrite su in place)
    float maxf = u2f(umax);
    float lsum = 0.f;
    for (int j = lane; j < m; j += 32) {
        int k = sidx[j];
        float p = __expf(u2f(su[k]) - maxf);
        su[k] = __float_as_uint(p);
        lsum += p;
    }
    __syncwarp();
    #pragma unroll
    for (int off = 16; off; off >>= 1) lsum += __shfl_xor_sync(0xffffffffu, lsum, off);
    float rinv = 1.0f / lsum;

    // ---- sparse PV
    const float2* V2 = reinterpret_cast<const float2*>(Vb);
    float2 y = make_float2(0.f, 0.f);
    int j = 0;
    for (; j + 4 <= m; j += 4) {
        int k0 = sidx[j + 0], k1 = sidx[j + 1], k2 = sidx[j + 2], k3 = sidx[j + 3];
        float p0 = __uint_as_float(su[k0]);
        float p1 = __uint_as_float(su[k1]);
        float p2 = __uint_as_float(su[k2]);
        float p3 = __uint_as_float(su[k3]);
        float2 v0 = V2[(size_t)k0 * 32 + lane];
        float2 v1 = V2[(size_t)k1 * 32 + lane];
        float2 v2 = V2[(size_t)k2 * 32 + lane];
        float2 v3 = V2[(size_t)k3 * 32 + lane];
        y.x += p0 * v0.x + p1 * v1.x + p2 * v2.x + p3 * v3.x;
        y.y += p0 * v0.y + p1 * v1.y + p2 * v2.y + p3 * v3.y;
    }
    for (; j < m; j++) {
        int k = sidx[j];
        float p = __uint_as_float(su[k]);
        float2 v = V2[(size_t)k * 32 + lane];
        y.x += p * v.x; y.y += p * v.y;
    }
    int b = bh >> 3, h = bh & 7;
    *reinterpret_cast<float2*>(Y + (size_t)(b * Tc + qi) * Cc + h * HDc + lane * 2) =
        make_float2(y.x * rinv, y.y * rinv);
}

// ---------------------------------------------------------------------------
extern "C" void kernel_launch(void* const* d_in, const int* in_sizes, int n_in,
                              void* d_out, int out_size)
{
    const float* q  = (const float*)d_in[0];
    const float* Wq = (const float*)d_in[2];
    const float* bq = (const float*)d_in[3];
    const float* Wk = (const float*)d_in[4];
    const float* bk = (const float*)d_in[5];
    const float* Wv = (const float*)d_in[6];
    const float* bv = (const float*)d_in[7];
    const float* Wp = (const float*)d_in[8];
    const float* bp = (const float*)d_in[9];

    float *Qh, *Kh, *Vh, *Yb;
    cudaGetSymbolAddress((void**)&Qh, g_Qh);
    cudaGetSymbolAddress((void**)&Kh, g_Kh);
    cudaGetSymbolAddress((void**)&Vh, g_Vh);
    cudaGetSymbolAddress((void**)&Yb, g_Y);

    cudaFuncSetAttribute(attn_kernel, cudaFuncAttributeMaxDynamicSharedMemorySize,
                         (int)sizeof(AttnSmem));

    qkv_kernel<<<dim3(Cc / 128, Mr / 128, 3), 256>>>(q, Wq, bq, Wk, bk, Wv, bv, Qh, Kh, Vh);
    attn_kernel<<<dim3(Tc / QT, BHc), 256, sizeof(AttnSmem)>>>(Qh, Kh, Vh, Yb);
    sgemm_kernel<<<dim3(Cc / 128, Mr / 128), 256>>>(Yb, Wp, bp, (float*)d_out);
}

// round 7
// speedup vs baseline: 2.3720x; 1.8331x over previous
#include <cuda_runtime.h>

#define Bc 2
#define Tc 2048
#define Cc 512
#define Hc 8
#define HDc 64
#define TOPKc 64
#define BHc (Bc*Hc)
#define Mr (Bc*Tc)
#define QT 8
#define KT 128

typedef unsigned long long ull;

// Scratch (device globals; allocations forbidden)
__device__ float g_Qh[BHc*Tc*HDc];
__device__ float g_Kh[BHc*Tc*HDc];
__device__ float g_Vh[BHc*Tc*HDc];
__device__ float g_Y [Bc*Tc*Cc];

// ---------------------------------------------------------------------------
// helpers
// ---------------------------------------------------------------------------
__device__ __forceinline__ unsigned f2u(float f) {
    unsigned b = __float_as_uint(f);
    return b ^ ((unsigned)((int)b >> 31) | 0x80000000u);
}
__device__ __forceinline__ float u2f(unsigned u) {
    unsigned b = (u & 0x80000000u) ? (u ^ 0x80000000u) : ~u;
    return __uint_as_float(b);
}
__device__ __forceinline__ ull packdup(float x) {
    ull d; asm("mov.b64 %0, {%1, %1};" : "=l"(d) : "f"(x)); return d;
}
__device__ __forceinline__ ull packpair(float x, float y) {
    ull d; asm("mov.b64 %0, {%1, %2};" : "=l"(d) : "f"(x), "f"(y)); return d;
}
__device__ __forceinline__ void fma2(ull& d, ull a, ull b, ull c) {
    asm("fma.rn.f32x2 %0, %1, %2, %3;" : "=l"(d) : "l"(a), "l"(b), "l"(c));
}
__device__ __forceinline__ float2 unpack2(ull v) {
    float x, y; asm("mov.b64 {%0, %1}, %2;" : "=f"(x), "=f"(y) : "l"(v));
    return make_float2(x, y);
}

// ---------------------------------------------------------------------------
// Fused QKV GEMM (measured 156us incl. fused v-norm). grid.z selects W/out.
// ---------------------------------------------------------------------------
__global__ void __launch_bounds__(256, 2)
qkv_kernel(const float* __restrict__ A,
           const float* __restrict__ Wq, const float* __restrict__ bq,
           const float* __restrict__ Wk, const float* __restrict__ bk,
           const float* __restrict__ Wv, const float* __restrict__ bv,
           float* __restrict__ Qh, float* __restrict__ Kh, float* __restrict__ Vh)
{
    int z = blockIdx.z;
    const float* W    = (z == 0) ? Wq : (z == 1) ? Wk : Wv;
    const float* bias = (z == 0) ? bq : (z == 1) ? bk : bv;
    float* out        = (z == 0) ? Qh : (z == 1) ? Kh : Vh;

    __shared__ float As[2][8][128];
    __shared__ float Bs[2][8][128];

    int tid = threadIdx.x;
    int bm = blockIdx.y * 128;
    int bn = blockIdx.x * 128;
    int ty = tid >> 4;
    int tx = tid & 15;

    int arow = tid >> 1;
    int akq  = (tid & 1) * 4;
    int brow = tid >> 5;
    int bcol = (tid & 31) * 4;

    const float* Ag = A + (size_t)(bm + arow) * Cc + akq;
    const float* Wg = W + (size_t)brow * Cc + bn + bcol;

    ull acc[8][4];
    #pragma unroll
    for (int i = 0; i < 8; i++)
        #pragma unroll
        for (int j = 0; j < 4; j++) acc[i][j] = 0ULL;

    {
        float4 av = *reinterpret_cast<const float4*>(Ag);
        float4 bv4 = *reinterpret_cast<const float4*>(Wg);
        As[0][akq + 0][arow] = av.x;
        As[0][akq + 1][arow] = av.y;
        As[0][akq + 2][arow] = av.z;
        As[0][akq + 3][arow] = av.w;
        *reinterpret_cast<float4*>(&Bs[0][brow][bcol]) = bv4;
    }
    __syncthreads();

    #pragma unroll 1
    for (int kb = 0; kb < 64; kb++) {
        int cur = kb & 1;
        float4 an, bnv;
        if (kb < 63) {
            an  = *reinterpret_cast<const float4*>(Ag + (kb + 1) * 8);
            bnv = *reinterpret_cast<const float4*>(Wg + (size_t)(kb + 1) * 8 * Cc);
        }
        #pragma unroll
        for (int k = 0; k < 8; k++) {
            float4 a0 = *reinterpret_cast<const float4*>(&As[cur][k][ty * 4]);
            float4 a1 = *reinterpret_cast<const float4*>(&As[cur][k][64 + ty * 4]);
            float4 b0 = *reinterpret_cast<const float4*>(&Bs[cur][k][tx * 4]);
            float4 b1 = *reinterpret_cast<const float4*>(&Bs[cur][k][64 + tx * 4]);
            ull bb[4] = { packpair(b0.x, b0.y), packpair(b0.z, b0.w),
                          packpair(b1.x, b1.y), packpair(b1.z, b1.w) };
            ull aa[8] = { packdup(a0.x), packdup(a0.y), packdup(a0.z), packdup(a0.w),
                          packdup(a1.x), packdup(a1.y), packdup(a1.z), packdup(a1.w) };
            #pragma unroll
            for (int i = 0; i < 8; i++)
                #pragma unroll
                for (int j = 0; j < 4; j++)
                    fma2(acc[i][j], aa[i], bb[j], acc[i][j]);
        }
        if (kb < 63) {
            int nxt = cur ^ 1;
            As[nxt][akq + 0][arow] = an.x;
            As[nxt][akq + 1][arow] = an.y;
            As[nxt][akq + 2][arow] = an.z;
            As[nxt][akq + 3][arow] = an.w;
            *reinterpret_cast<float4*>(&Bs[nxt][brow][bcol]) = bnv;
            __syncthreads();
        }
    }

    float4 bia0 = *reinterpret_cast<const float4*>(bias + bn + tx * 4);
    float4 bia1 = *reinterpret_cast<const float4*>(bias + bn + 64 + tx * 4);
    #pragma unroll
    for (int i = 0; i < 8; i++) {
        int r = (i < 4) ? (ty * 4 + i) : (64 + ty * 4 + (i - 4));
        int mrow = bm + r;
        int b = mrow >> 11;
        int t = mrow & (Tc - 1);
        float2 c0 = unpack2(acc[i][0]);
        float2 c1 = unpack2(acc[i][1]);
        float2 c2 = unpack2(acc[i][2]);
        float2 c3 = unpack2(acc[i][3]);
        float4 o0 = make_float4(c0.x + bia0.x, c0.y + bia0.y, c1.x + bia0.z, c1.y + bia0.w);
        float4 o1 = make_float4(c2.x + bia1.x, c2.y + bia1.y, c3.x + bia1.z, c3.y + bia1.w);
        if (z == 2) {
            float ss0 = o0.x*o0.x + o0.y*o0.y + o0.z*o0.z + o0.w*o0.w;
            float ss1 = o1.x*o1.x + o1.y*o1.y + o1.z*o1.z + o1.w*o1.w;
            #pragma unroll
            for (int off = 8; off; off >>= 1) {
                ss0 += __shfl_xor_sync(0xffffffffu, ss0, off);
                ss1 += __shfl_xor_sync(0xffffffffu, ss1, off);
            }
            float sc0 = 1.0f / fmaxf(sqrtf(ss0), 1e-12f);
            float sc1 = 1.0f / fmaxf(sqrtf(ss1), 1e-12f);
            o0.x *= sc0; o0.y *= sc0; o0.z *= sc0; o0.w *= sc0;
            o1.x *= sc1; o1.y *= sc1; o1.z *= sc1; o1.w *= sc1;
        }
        int n0 = bn + tx * 4;       int h0 = n0 >> 6, d0 = n0 & 63;
        int n1 = bn + 64 + tx * 4;  int h1 = n1 >> 6, d1 = n1 & 63;
        *reinterpret_cast<float4*>(out + ((size_t)((b * Hc + h0) * Tc + t) << 6) + d0) = o0;
        *reinterpret_cast<float4*>(out + ((size_t)((b * Hc + h1) * Tc + t) << 6) + d1) = o1;
    }
}

// ---------------------------------------------------------------------------
// Output projection GEMM (row-major out).
// ---------------------------------------------------------------------------
__global__ void __launch_bounds__(256, 2)
sgemm_kernel(const float* __restrict__ A, const float* __restrict__ W,
             const float* __restrict__ bias, float* __restrict__ out)
{
    __shared__ float As[2][8][128];
    __shared__ float Bs[2][8][128];

    int tid = threadIdx.x;
    int bm = blockIdx.y * 128;
    int bn = blockIdx.x * 128;
    int ty = tid >> 4;
    int tx = tid & 15;

    int arow = tid >> 1;
    int akq  = (tid & 1) * 4;
    int brow = tid >> 5;
    int bcol = (tid & 31) * 4;

    const float* Ag = A + (size_t)(bm + arow) * Cc + akq;
    const float* Wg = W + (size_t)brow * Cc + bn + bcol;

    ull acc[8][4];
    #pragma unroll
    for (int i = 0; i < 8; i++)
        #pragma unroll
        for (int j = 0; j < 4; j++) acc[i][j] = 0ULL;

    {
        float4 av = *reinterpret_cast<const float4*>(Ag);
        float4 bv4 = *reinterpret_cast<const float4*>(Wg);
        As[0][akq + 0][arow] = av.x;
        As[0][akq + 1][arow] = av.y;
        As[0][akq + 2][arow] = av.z;
        As[0][akq + 3][arow] = av.w;
        *reinterpret_cast<float4*>(&Bs[0][brow][bcol]) = bv4;
    }
    __syncthreads();

    #pragma unroll 1
    for (int kb = 0; kb < 64; kb++) {
        int cur = kb & 1;
        float4 an, bnv;
        if (kb < 63) {
            an  = *reinterpret_cast<const float4*>(Ag + (kb + 1) * 8);
            bnv = *reinterpret_cast<const float4*>(Wg + (size_t)(kb + 1) * 8 * Cc);
        }
        #pragma unroll
        for (int k = 0; k < 8; k++) {
            float4 a0 = *reinterpret_cast<const float4*>(&As[cur][k][ty * 4]);
            float4 a1 = *reinterpret_cast<const float4*>(&As[cur][k][64 + ty * 4]);
            float4 b0 = *reinterpret_cast<const float4*>(&Bs[cur][k][tx * 4]);
            float4 b1 = *reinterpret_cast<const float4*>(&Bs[cur][k][64 + tx * 4]);
            ull bb[4] = { packpair(b0.x, b0.y), packpair(b0.z, b0.w),
                          packpair(b1.x, b1.y), packpair(b1.z, b1.w) };
            ull aa[8] = { packdup(a0.x), packdup(a0.y), packdup(a0.z), packdup(a0.w),
                          packdup(a1.x), packdup(a1.y), packdup(a1.z), packdup(a1.w) };
            #pragma unroll
            for (int i = 0; i < 8; i++)
                #pragma unroll
                for (int j = 0; j < 4; j++)
                    fma2(acc[i][j], aa[i], bb[j], acc[i][j]);
        }
        if (kb < 63) {
            int nxt = cur ^ 1;
            As[nxt][akq + 0][arow] = an.x;
            As[nxt][akq + 1][arow] = an.y;
            As[nxt][akq + 2][arow] = an.z;
            As[nxt][akq + 3][arow] = an.w;
            *reinterpret_cast<float4*>(&Bs[nxt][brow][bcol]) = bnv;
            __syncthreads();
        }
    }

    float4 bia0 = *reinterpret_cast<const float4*>(bias + bn + tx * 4);
    float4 bia1 = *reinterpret_cast<const float4*>(bias + bn + 64 + tx * 4);
    #pragma unroll
    for (int i = 0; i < 8; i++) {
        int r = (i < 4) ? (ty * 4 + i) : (64 + ty * 4 + (i - 4));
        int mrow = bm + r;
        float2 c0 = unpack2(acc[i][0]);
        float2 c1 = unpack2(acc[i][1]);
        float2 c2 = unpack2(acc[i][2]);
        float2 c3 = unpack2(acc[i][3]);
        float4 o0 = make_float4(c0.x + bia0.x, c0.y + bia0.y, c1.x + bia0.z, c1.y + bia0.w);
        float4 o1 = make_float4(c2.x + bia1.x, c2.y + bia1.y, c3.x + bia1.z, c3.y + bia1.w);
        *reinterpret_cast<float4*>(out + (size_t)mrow * Cc + bn + tx * 4) = o0;
        *reinterpret_cast<float4*>(out + (size_t)mrow * Cc + bn + 64 + tx * 4) = o1;
    }
}

// ---------------------------------------------------------------------------
// Attention: round-3 structure (QT=8, 2 blocks/SM, atomics radix select,
// direct tile loads, single kt buffer). ONLY change vs round 3: score phase
// maps warp w -> 2 rows {2(w&3), 2(w&3)+1} x key-half (w>>2), so each kv
// LDS.128 feeds 8 FFMA instead of 4 (halved crossbar traffic).
// ---------------------------------------------------------------------------
struct AttnSmem {
    float qs[QT][HDc];                 // 2 KB
    float kt[KT][68];                  // 34.8 KB
    unsigned su[QT][Tc];               // 64 KB scores / probs
    union RowSel {
        int hist[256];
        unsigned short sidx[512];
    } sel[QT];                         // 8 KB
};

__global__ void __launch_bounds__(256, 2)
attn_kernel(const float* __restrict__ Q, const float* __restrict__ K,
            const float* __restrict__ V, float* __restrict__ Y)
{
    extern __shared__ unsigned char raw[];
    AttnSmem* S = reinterpret_cast<AttnSmem*>(raw);

    int tid  = threadIdx.x;
    int warp = tid >> 5;
    int lane = tid & 31;

    int bh = blockIdx.y;
    int qbase = ((int)gridDim.x - 1 - (int)blockIdx.x) * QT;  // long rows first
    int n_max = qbase + QT;

    const float* Kb = K + (size_t)bh * Tc * HDc;
    const float* Vb = V + (size_t)bh * Tc * HDc;

    if (tid < 128) {
        int r = tid >> 4, i = tid & 15;
        reinterpret_cast<float4*>(S->qs[r])[i] =
            reinterpret_cast<const float4*>(Q + ((size_t)bh * Tc + qbase + r) * HDc)[i];
    }

    // score-phase mapping: 2 rows x half the keys per warp
    int half  = warp >> 2;              // 0/1 -> key half
    int rpair = (warp & 3) * 2;         // row pair base
    int qiA = qbase + rpair;
    int qiB = qiA + 1;
    const float4* q4a = reinterpret_cast<const float4*>(S->qs[rpair]);
    const float4* q4b = reinterpret_cast<const float4*>(S->qs[rpair + 1]);

    #pragma unroll 1
    for (int t0 = 0; t0 < n_max; t0 += KT) {
        __syncthreads();
        #pragma unroll
        for (int i = 0; i < 8; i++) {
            int idx = tid + 256 * i;
            int kk = idx >> 4, dq = idx & 15;
            float4 v = *reinterpret_cast<const float4*>(Kb + (size_t)(t0 + kk) * HDc + dq * 4);
            *reinterpret_cast<float4*>(&S->kt[kk][dq * 4]) = v;
        }
        __syncthreads();

        float a0[2] = {0.f, 0.f}, a1[2] = {0.f, 0.f};
        #pragma unroll
        for (int i = 0; i < 16; i++) {
            float4 qa = q4a[i];
            float4 qb = q4b[i];
            #pragma unroll
            for (int j = 0; j < 2; j++) {
                float4 kv = *reinterpret_cast<const float4*>(
                    &S->kt[half * 64 + lane + 32 * j][i * 4]);
                a0[j] += qa.x * kv.x + qa.y * kv.y + qa.z * kv.z + qa.w * kv.w;
                a1[j] += qb.x * kv.x + qb.y * kv.y + qb.z * kv.z + qb.w * kv.w;
            }
        }
        #pragma unroll
        for (int j = 0; j < 2; j++) {
            int k = t0 + half * 64 + lane + 32 * j;
            if (k <= qiA) S->su[rpair][k]     = f2u(a0[j] * 0.125f);
            if (k <= qiB) S->su[rpair + 1][k] = f2u(a1[j] * 0.125f);
        }
    }
    __syncthreads();   // all scores visible; switch to warp<->row mapping

    int row = warp;
    int qi = qbase + row;
    int n = qi + 1;
    unsigned* su = S->su[row];

    // ---- exact rank-64 threshold: 4-pass byte radix (round-3 atomics form)
    unsigned thrU = 0u;
    if (n > TOPKc) {
        unsigned pref = 0u; int need = TOPKc;
        #pragma unroll 1
        for (int by = 3; by >= 0; --by) {
            int sh = by * 8;
            #pragma unroll
            for (int b = lane; b < 256; b += 32) S->sel[row].hist[b] = 0;
            __syncwarp();
            if (by == 3) {
                for (int k = lane; k < n; k += 32) {
                    unsigned u = su[k];
                    atomicAdd(&S->sel[row].hist[u >> 24], 1);
                }
            } else {
                unsigned hp = pref >> (sh + 8);
                for (int k = lane; k < n; k += 32) {
                    unsigned u = su[k];
                    if ((u >> (sh + 8)) == hp)
                        atomicAdd(&S->sel[row].hist[(u >> sh) & 255u], 1);
                }
            }
            __syncwarp();
            int s = 0;
            #pragma unroll
            for (int j = 0; j < 8; j++) s += S->sel[row].hist[255 - lane * 8 - j];
            int cum = s;
            #pragma unroll
            for (int off = 1; off < 32; off <<= 1) {
                int v = __shfl_up_sync(0xffffffffu, cum, off);
                if (lane >= off) cum += v;
            }
            unsigned bal = __ballot_sync(0xffffffffu, cum >= need);
            int selL = __ffs(bal) - 1;
            int above = __shfl_sync(0xffffffffu, cum - s, selL);
            int sneed = need - above;
            int res = 0;
            if (lane == selL) {
                int c = 0;
                #pragma unroll 1
                for (int j = 0; j < 8; j++) {
                    int b = 255 - selL * 8 - j;
                    int h = S->sel[row].hist[b];
                    if (c + h >= sneed) { res = (b << 16) | (sneed - c); break; }
                    c += h;
                }
            }
            res = __shfl_sync(0xffffffffu, res, selL);
            pref |= (unsigned)(res >> 16) << sh;
            need = res & 0xffff;
        }
        thrU = pref;
    }
    __syncwarp();

    // ---- ballot compaction (ordered) + row max
    unsigned short* sidx = S->sel[row].sidx;
    int m = 0; unsigned umax = 0u;
    #pragma unroll 1
    for (int k0 = 0; k0 < n; k0 += 32) {
        int k = k0 + lane;
        bool a = k < n;
        unsigned u = a ? su[k] : 0u;
        umax = max(umax, u);
        bool keep = a && (u >= thrU);
        unsigned bal = __ballot_sync(0xffffffffu, keep);
        if (keep) {
            int pos = m + __popc(bal & ((1u << lane) - 1u));
            if (pos < 512) sidx[pos] = (unsigned short)k;
        }
        m += __popc(bal);
    }
    if (m > 512) m = 512;
    #pragma unroll
    for (int off = 16; off; off >>= 1)
        umax = max(umax, __shfl_xor_sync(0xffffffffu, umax, off));

    // ---- softmax over survivors (probs overwrite su in place)
    float maxf = u2f(umax);
    float lsum = 0.f;
    for (int j = lane; j < m; j += 32) {
        int k = sidx[j];
        float p = __expf(u2f(su[k]) - maxf);
        su[k] = __float_as_uint(p);
        lsum += p;
    }
    __syncwarp();
    #pragma unroll
    for (int off = 16; off; off >>= 1) lsum += __shfl_xor_sync(0xffffffffu, lsum, off);
    float rinv = 1.0f / lsum;

    // ---- sparse PV
    const float2* V2 = reinterpret_cast<const float2*>(Vb);
    float2 y = make_float2(0.f, 0.f);
    int j = 0;
    for (; j + 4 <= m; j += 4) {
        int k0 = sidx[j + 0], k1 = sidx[j + 1], k2 = sidx[j + 2], k3 = sidx[j + 3];
        float p0 = __uint_as_float(su[k0]);
        float p1 = __uint_as_float(su[k1]);
        float p2 = __uint_as_float(su[k2]);
        float p3 = __uint_as_float(su[k3]);
        float2 v0 = V2[(size_t)k0 * 32 + lane];
        float2 v1 = V2[(size_t)k1 * 32 + lane];
        float2 v2 = V2[(size_t)k2 * 32 + lane];
        float2 v3 = V2[(size_t)k3 * 32 + lane];
        y.x += p0 * v0.x + p1 * v1.x + p2 * v2.x + p3 * v3.x;
        y.y += p0 * v0.y + p1 * v1.y + p2 * v2.y + p3 * v3.y;
    }
    for (; j < m; j++) {
        int k = sidx[j];
        float p = __uint_as_float(su[k]);
        float2 v = V2[(size_t)k * 32 + lane];
        y.x += p * v.x; y.y += p * v.y;
    }
    int b = bh >> 3, h = bh & 7;
    *reinterpret_cast<float2*>(Y + (size_t)(b * Tc + qi) * Cc + h * HDc + lane * 2) =
        make_float2(y.x * rinv, y.y * rinv);
}

// ---------------------------------------------------------------------------
extern "C" void kernel_launch(void* const* d_in, const int* in_sizes, int n_in,
                              void* d_out, int out_size)
{
    const float* q  = (const float*)d_in[0];
    const float* Wq = (const float*)d_in[2];
    const float* bq = (const float*)d_in[3];
    const float* Wk = (const float*)d_in[4];
    const float* bk = (const float*)d_in[5];
    const float* Wv = (const float*)d_in[6];
    const float* bv = (const float*)d_in[7];
    const float* Wp = (const float*)d_in[8];
    const float* bp = (const float*)d_in[9];

    float *Qh, *Kh, *Vh, *Yb;
    cudaGetSymbolAddress((void**)&Qh, g_Qh);
    cudaGetSymbolAddress((void**)&Kh, g_Kh);
    cudaGetSymbolAddress((void**)&Vh, g_Vh);
    cudaGetSymbolAddress((void**)&Yb, g_Y);

    cudaFuncSetAttribute(attn_kernel, cudaFuncAttributeMaxDynamicSharedMemorySize,
                         (int)sizeof(AttnSmem));

    qkv_kernel<<<dim3(Cc / 128, Mr / 128, 3), 256>>>(q, Wq, bq, Wk, bk, Wv, bv, Qh, Kh, Vh);
    attn_kernel<<<dim3(Tc / QT, BHc), 256, sizeof(AttnSmem)>>>(Qh, Kh, Vh, Yb);
    sgemm_kernel<<<dim3(Cc / 128, Mr / 128), 256>>>(Yb, Wp, bp, (float*)d_out);
}

// round 8
// speedup vs baseline: 2.4578x; 1.0362x over previous
#include <cuda_runtime.h>

#define Bc 2
#define Tc 2048
#define Cc 512
#define Hc 8
#define HDc 64
#define TOPKc 64
#define BHc (Bc*Hc)
#define Mr (Bc*Tc)
#define QT 8
#define KT 128

// Scratch (device globals; allocations forbidden)
__device__ float g_Qh[BHc*Tc*HDc];
__device__ float g_Kh[BHc*Tc*HDc];
__device__ float g_Vh[BHc*Tc*HDc];
__device__ float g_Y [Bc*Tc*Cc];

// ---------------------------------------------------------------------------
// helpers
// ---------------------------------------------------------------------------
__device__ __forceinline__ unsigned f2u(float f) {
    unsigned b = __float_as_uint(f);
    return b ^ ((unsigned)((int)b >> 31) | 0x80000000u);
}
__device__ __forceinline__ float u2f(unsigned u) {
    unsigned b = (u & 0x80000000u) ? (u ^ 0x80000000u) : ~u;
    return __uint_as_float(b);
}

// ---------------------------------------------------------------------------
// Fused QKV GEMM: grid.z selects W/out. BM=BN=128, BK=8, 256 thr, scalar FFMA
// 8x8 micro, double buffer. z==2 (V): fused per-head row-norm in epilogue.
// ---------------------------------------------------------------------------
__global__ void __launch_bounds__(256, 2)
qkv_kernel(const float* __restrict__ A,
           const float* __restrict__ Wq, const float* __restrict__ bq,
           const float* __restrict__ Wk, const float* __restrict__ bk,
           const float* __restrict__ Wv, const float* __restrict__ bv,
           float* __restrict__ Qh, float* __restrict__ Kh, float* __restrict__ Vh)
{
    int z = blockIdx.z;
    const float* W    = (z == 0) ? Wq : (z == 1) ? Wk : Wv;
    const float* bias = (z == 0) ? bq : (z == 1) ? bk : bv;
    float* out        = (z == 0) ? Qh : (z == 1) ? Kh : Vh;

    __shared__ float As[2][8][128];
    __shared__ float Bs[2][8][128];

    int tid = threadIdx.x;
    int bm = blockIdx.y * 128;
    int bn = blockIdx.x * 128;
    int ty = tid >> 4;
    int tx = tid & 15;

    int arow = tid >> 1;
    int akq  = (tid & 1) * 4;
    int brow = tid >> 5;
    int bcol = (tid & 31) * 4;

    const float* Ag = A + (size_t)(bm + arow) * Cc + akq;
    const float* Wg = W + (size_t)brow * Cc + bn + bcol;

    float acc[8][8];
    #pragma unroll
    for (int i = 0; i < 8; i++)
        #pragma unroll
        for (int j = 0; j < 8; j++) acc[i][j] = 0.f;

    {
        float4 av = *reinterpret_cast<const float4*>(Ag);
        float4 bv4 = *reinterpret_cast<const float4*>(Wg);
        As[0][akq + 0][arow] = av.x;
        As[0][akq + 1][arow] = av.y;
        As[0][akq + 2][arow] = av.z;
        As[0][akq + 3][arow] = av.w;
        *reinterpret_cast<float4*>(&Bs[0][brow][bcol]) = bv4;
    }
    __syncthreads();

    #pragma unroll 1
    for (int kb = 0; kb < 64; kb++) {
        int cur = kb & 1;
        float4 an, bnv;
        if (kb < 63) {
            an  = *reinterpret_cast<const float4*>(Ag + (kb + 1) * 8);
            bnv = *reinterpret_cast<const float4*>(Wg + (size_t)(kb + 1) * 8 * Cc);
        }
        #pragma unroll
        for (int k = 0; k < 8; k++) {
            float4 a0 = *reinterpret_cast<const float4*>(&As[cur][k][ty * 4]);
            float4 a1 = *reinterpret_cast<const float4*>(&As[cur][k][64 + ty * 4]);
            float4 b0 = *reinterpret_cast<const float4*>(&Bs[cur][k][tx * 4]);
            float4 b1 = *reinterpret_cast<const float4*>(&Bs[cur][k][64 + tx * 4]);
            float a[8] = {a0.x, a0.y, a0.z, a0.w, a1.x, a1.y, a1.z, a1.w};
            float b[8] = {b0.x, b0.y, b0.z, b0.w, b1.x, b1.y, b1.z, b1.w};
            #pragma unroll
            for (int i = 0; i < 8; i++)
                #pragma unroll
                for (int j = 0; j < 8; j++)
                    acc[i][j] += a[i] * b[j];
        }
        if (kb < 63) {
            int nxt = cur ^ 1;
            As[nxt][akq + 0][arow] = an.x;
            As[nxt][akq + 1][arow] = an.y;
            As[nxt][akq + 2][arow] = an.z;
            As[nxt][akq + 3][arow] = an.w;
            *reinterpret_cast<float4*>(&Bs[nxt][brow][bcol]) = bnv;
            __syncthreads();
        }
    }

    float4 bia0 = *reinterpret_cast<const float4*>(bias + bn + tx * 4);
    float4 bia1 = *reinterpret_cast<const float4*>(bias + bn + 64 + tx * 4);
    #pragma unroll
    for (int i = 0; i < 8; i++) {
        int r = (i < 4) ? (ty * 4 + i) : (64 + ty * 4 + (i - 4));
        int mrow = bm + r;
        int b = mrow >> 11;
        int t = mrow & (Tc - 1);
        float4 o0 = make_float4(acc[i][0] + bia0.x, acc[i][1] + bia0.y,
                                acc[i][2] + bia0.z, acc[i][3] + bia0.w);
        float4 o1 = make_float4(acc[i][4] + bia1.x, acc[i][5] + bia1.y,
                                acc[i][6] + bia1.z, acc[i][7] + bia1.w);
        if (z == 2) {
            float ss0 = o0.x*o0.x + o0.y*o0.y + o0.z*o0.z + o0.w*o0.w;
            float ss1 = o1.x*o1.x + o1.y*o1.y + o1.z*o1.z + o1.w*o1.w;
            #pragma unroll
            for (int off = 8; off; off >>= 1) {
                ss0 += __shfl_xor_sync(0xffffffffu, ss0, off);
                ss1 += __shfl_xor_sync(0xffffffffu, ss1, off);
            }
            float sc0 = 1.0f / fmaxf(sqrtf(ss0), 1e-12f);
            float sc1 = 1.0f / fmaxf(sqrtf(ss1), 1e-12f);
            o0.x *= sc0; o0.y *= sc0; o0.z *= sc0; o0.w *= sc0;
            o1.x *= sc1; o1.y *= sc1; o1.z *= sc1; o1.w *= sc1;
        }
        int n0 = bn + tx * 4;       int h0 = n0 >> 6, d0 = n0 & 63;
        int n1 = bn + 64 + tx * 4;  int h1 = n1 >> 6, d1 = n1 & 63;
        *reinterpret_cast<float4*>(out + ((size_t)((b * Hc + h0) * Tc + t) << 6) + d0) = o0;
        *reinterpret_cast<float4*>(out + ((size_t)((b * Hc + h1) * Tc + t) << 6) + d1) = o1;
    }
}

// ---------------------------------------------------------------------------
// Output projection GEMM (row-major out), scalar FFMA.
// ---------------------------------------------------------------------------
__global__ void __launch_bounds__(256, 2)
sgemm_kernel(const float* __restrict__ A, const float* __restrict__ W,
             const float* __restrict__ bias, float* __restrict__ out)
{
    __shared__ float As[2][8][128];
    __shared__ float Bs[2][8][128];

    int tid = threadIdx.x;
    int bm = blockIdx.y * 128;
    int bn = blockIdx.x * 128;
    int ty = tid >> 4;
    int tx = tid & 15;

    int arow = tid >> 1;
    int akq  = (tid & 1) * 4;
    int brow = tid >> 5;
    int bcol = (tid & 31) * 4;

    const float* Ag = A + (size_t)(bm + arow) * Cc + akq;
    const float* Wg = W + (size_t)brow * Cc + bn + bcol;

    float acc[8][8];
    #pragma unroll
    for (int i = 0; i < 8; i++)
        #pragma unroll
        for (int j = 0; j < 8; j++) acc[i][j] = 0.f;

    {
        float4 av = *reinterpret_cast<const float4*>(Ag);
        float4 bv4 = *reinterpret_cast<const float4*>(Wg);
        As[0][akq + 0][arow] = av.x;
        As[0][akq + 1][arow] = av.y;
        As[0][akq + 2][arow] = av.z;
        As[0][akq + 3][arow] = av.w;
        *reinterpret_cast<float4*>(&Bs[0][brow][bcol]) = bv4;
    }
    __syncthreads();

    #pragma unroll 1
    for (int kb = 0; kb < 64; kb++) {
        int cur = kb & 1;
        float4 an, bnv;
        if (kb < 63) {
            an  = *reinterpret_cast<const float4*>(Ag + (kb + 1) * 8);
            bnv = *reinterpret_cast<const float4*>(Wg + (size_t)(kb + 1) * 8 * Cc);
        }
        #pragma unroll
        for (int k = 0; k < 8; k++) {
            float4 a0 = *reinterpret_cast<const float4*>(&As[cur][k][ty * 4]);
            float4 a1 = *reinterpret_cast<const float4*>(&As[cur][k][64 + ty * 4]);
            float4 b0 = *reinterpret_cast<const float4*>(&Bs[cur][k][tx * 4]);
            float4 b1 = *reinterpret_cast<const float4*>(&Bs[cur][k][64 + tx * 4]);
            float a[8] = {a0.x, a0.y, a0.z, a0.w, a1.x, a1.y, a1.z, a1.w};
            float b[8] = {b0.x, b0.y, b0.z, b0.w, b1.x, b1.y, b1.z, b1.w};
            #pragma unroll
            for (int i = 0; i < 8; i++)
                #pragma unroll
                for (int j = 0; j < 8; j++)
                    acc[i][j] += a[i] * b[j];
        }
        if (kb < 63) {
            int nxt = cur ^ 1;
            As[nxt][akq + 0][arow] = an.x;
            As[nxt][akq + 1][arow] = an.y;
            As[nxt][akq + 2][arow] = an.z;
            As[nxt][akq + 3][arow] = an.w;
            *reinterpret_cast<float4*>(&Bs[nxt][brow][bcol]) = bnv;
            __syncthreads();
        }
    }

    float4 bia0 = *reinterpret_cast<const float4*>(bias + bn + tx * 4);
    float4 bia1 = *reinterpret_cast<const float4*>(bias + bn + 64 + tx * 4);
    #pragma unroll
    for (int i = 0; i < 8; i++) {
        int r = (i < 4) ? (ty * 4 + i) : (64 + ty * 4 + (i - 4));
        int mrow = bm + r;
        float4 o0 = make_float4(acc[i][0] + bia0.x, acc[i][1] + bia0.y,
                                acc[i][2] + bia0.z, acc[i][3] + bia0.w);
        float4 o1 = make_float4(acc[i][4] + bia1.x, acc[i][5] + bia1.y,
                                acc[i][6] + bia1.z, acc[i][7] + bia1.w);
        *reinterpret_cast<float4*>(out + (size_t)mrow * Cc + bn + tx * 4) = o0;
        *reinterpret_cast<float4*>(out + (size_t)mrow * Cc + bn + 64 + tx * 4) = o1;
    }
}

// ---------------------------------------------------------------------------
// Attention: QT=8, 2 blocks/SM. Score phase: warp w -> 4 rows {(w&1)*4..+3}
// x key-quarter (w>>1): each kv LDS.128 feeds 16 FFMA (4 rows). Next K tile
// prefetched into registers during compute. Select/compact/softmax/PV
// identical to round 7.
// ---------------------------------------------------------------------------
struct AttnSmem {
    float qs[QT][HDc];                 // 2 KB
    float kt[KT][68];                  // 34.8 KB
    unsigned su[QT][Tc];               // 64 KB scores / probs
    union RowSel {
        int hist[256];
        unsigned short sidx[512];
    } sel[QT];                         // 8 KB
};

__global__ void __launch_bounds__(256, 2)
attn_kernel(const float* __restrict__ Q, const float* __restrict__ K,
            const float* __restrict__ V, float* __restrict__ Y)
{
    extern __shared__ unsigned char raw[];
    AttnSmem* S = reinterpret_cast<AttnSmem*>(raw);

    int tid  = threadIdx.x;
    int warp = tid >> 5;
    int lane = tid & 31;

    int bh = blockIdx.y;
    int qbase = ((int)gridDim.x - 1 - (int)blockIdx.x) * QT;  // long rows first
    int n_max = qbase + QT;

    const float* Kb = K + (size_t)bh * Tc * HDc;
    const float* Vb = V + (size_t)bh * Tc * HDc;

    if (tid < 128) {
        int r = tid >> 4, i = tid & 15;
        reinterpret_cast<float4*>(S->qs[r])[i] =
            reinterpret_cast<const float4*>(Q + ((size_t)bh * Tc + qbase + r) * HDc)[i];
    }

    // score-phase mapping: 4 rows x quarter keys per warp
    int quarter = warp >> 1;            // 0..3 -> key quarter
    int rgrp = (warp & 1) * 4;          // row group base (4 rows)
    int kqoff = quarter * 32 + lane;    // key offset within tile
    const float4* q40 = reinterpret_cast<const float4*>(S->qs[rgrp + 0]);
    const float4* q41 = reinterpret_cast<const float4*>(S->qs[rgrp + 1]);
    const float4* q42 = reinterpret_cast<const float4*>(S->qs[rgrp + 2]);
    const float4* q43 = reinterpret_cast<const float4*>(S->qs[rgrp + 3]);

    int ldrow = tid >> 4;               // 0..15
    int lddq  = (tid & 15) * 4;

    int ntiles = (n_max + KT - 1) / KT;

    // prologue: tile 0 -> registers
    float4 rv[8];
    #pragma unroll
    for (int i = 0; i < 8; i++)
        rv[i] = *reinterpret_cast<const float4*>(Kb + (size_t)(ldrow + 16 * i) * HDc + lddq);

    #pragma unroll 1
    for (int t = 0; t < ntiles; t++) {
        __syncthreads();
        #pragma unroll
        for (int i = 0; i < 8; i++)
            *reinterpret_cast<float4*>(&S->kt[ldrow + 16 * i][lddq]) = rv[i];
        __syncthreads();

        if (t + 1 < ntiles) {
            int t0n = (t + 1) * KT;
            #pragma unroll
            for (int i = 0; i < 8; i++)
                rv[i] = *reinterpret_cast<const float4*>(
                            Kb + (size_t)(t0n + ldrow + 16 * i) * HDc + lddq);
        }

        float a0 = 0.f, a1 = 0.f, a2 = 0.f, a3 = 0.f;
        #pragma unroll
        for (int i = 0; i < 16; i++) {
            float4 kv = *reinterpret_cast<const float4*>(&S->kt[kqoff][i * 4]);
            float4 qa = q40[i], qb = q41[i], qc = q42[i], qd = q43[i];
            a0 += qa.x * kv.x + qa.y * kv.y + qa.z * kv.z + qa.w * kv.w;
            a1 += qb.x * kv.x + qb.y * kv.y + qb.z * kv.z + qb.w * kv.w;
            a2 += qc.x * kv.x + qc.y * kv.y + qc.z * kv.z + qc.w * kv.w;
            a3 += qd.x * kv.x + qd.y * kv.y + qd.z * kv.z + qd.w * kv.w;
        }
        int k = t * KT + kqoff;
        if (k <= qbase + rgrp + 0) S->su[rgrp + 0][k] = f2u(a0 * 0.125f);
        if (k <= qbase + rgrp + 1) S->su[rgrp + 1][k] = f2u(a1 * 0.125f);
        if (k <= qbase + rgrp + 2) S->su[rgrp + 2][k] = f2u(a2 * 0.125f);
        if (k <= qbase + rgrp + 3) S->su[rgrp + 3][k] = f2u(a3 * 0.125f);
    }
    __syncthreads();   // all scores visible; switch to warp<->row mapping

    int row = warp;
    int qi = qbase + row;
    int n = qi + 1;
    unsigned* su = S->su[row];

    // ---- exact rank-64 threshold: 4-pass byte radix (atomics form)
    unsigned thrU = 0u;
    if (n > TOPKc) {
        unsigned pref = 0u; int need = TOPKc;
        #pragma unroll 1
        for (int by = 3; by >= 0; --by) {
            int sh = by * 8;
            #pragma unroll
            for (int b = lane; b < 256; b += 32) S->sel[row].hist[b] = 0;
            __syncwarp();
            if (by == 3) {
                for (int k = lane; k < n; k += 32) {
                    unsigned u = su[k];
                    atomicAdd(&S->sel[row].hist[u >> 24], 1);
                }
            } else {
                unsigned hp = pref >> (sh + 8);
                for (int k = lane; k < n; k += 32) {
                    unsigned u = su[k];
                    if ((u >> (sh + 8)) == hp)
                        atomicAdd(&S->sel[row].hist[(u >> sh) & 255u], 1);
                }
            }
            __syncwarp();
            int s = 0;
            #pragma unroll
            for (int j = 0; j < 8; j++) s += S->sel[row].hist[255 - lane * 8 - j];
            int cum = s;
            #pragma unroll
            for (int off = 1; off < 32; off <<= 1) {
                int v = __shfl_up_sync(0xffffffffu, cum, off);
                if (lane >= off) cum += v;
            }
            unsigned bal = __ballot_sync(0xffffffffu, cum >= need);
            int selL = __ffs(bal) - 1;
            int above = __shfl_sync(0xffffffffu, cum - s, selL);
            int sneed = need - above;
            int res = 0;
            if (lane == selL) {
                int c = 0;
                #pragma unroll 1
                for (int j = 0; j < 8; j++) {
                    int b = 255 - selL * 8 - j;
                    int h = S->sel[row].hist[b];
                    if (c + h >= sneed) { res = (b << 16) | (sneed - c); break; }
                    c += h;
                }
            }
            res = __shfl_sync(0xffffffffu, res, selL);
            pref |= (unsigned)(res >> 16) << sh;
            need = res & 0xffff;
        }
        thrU = pref;
    }
    __syncwarp();

    // ---- ballot compaction (ordered) + row max
    unsigned short* sidx = S->sel[row].sidx;
    int m = 0; unsigned umax = 0u;
    #pragma unroll 1
    for (int k0 = 0; k0 < n; k0 += 32) {
        int k = k0 + lane;
        bool a = k < n;
        unsigned u = a ? su[k] : 0u;
        umax = max(umax, u);
        bool keep = a && (u >= thrU);
        unsigned bal = __ballot_sync(0xffffffffu, keep);
        if (keep) {
            int pos = m + __popc(bal & ((1u << lane) - 1u));
            if (pos < 512) sidx[pos] = (unsigned short)k;
        }
        m += __popc(bal);
    }
    if (m > 512) m = 512;
    #pragma unroll
    for (int off = 16; off; off >>= 1)
        umax = max(umax, __shfl_xor_sync(0xffffffffu, umax, off));

    // ---- softmax over survivors (probs overwrite su in place)
    float maxf = u2f(umax);
    float lsum = 0.f;
    for (int j = lane; j < m; j += 32) {
        int k = sidx[j];
        float p = __expf(u2f(su[k]) - maxf);
        su[k] = __float_as_uint(p);
        lsum += p;
    }
    __syncwarp();
    #pragma unroll
    for (int off = 16; off; off >>= 1) lsum += __shfl_xor_sync(0xffffffffu, lsum, off);
    float rinv = 1.0f / lsum;

    // ---- sparse PV
    const float2* V2 = reinterpret_cast<const float2*>(Vb);
    float2 y = make_float2(0.f, 0.f);
    int j = 0;
    for (; j + 4 <= m; j += 4) {
        int k0 = sidx[j + 0], k1 = sidx[j + 1], k2 = sidx[j + 2], k3 = sidx[j + 3];
        float p0 = __uint_as_float(su[k0]);
        float p1 = __uint_as_float(su[k1]);
        float p2 = __uint_as_float(su[k2]);
        float p3 = __uint_as_float(su[k3]);
        float2 v0 = V2[(size_t)k0 * 32 + lane];
        float2 v1 = V2[(size_t)k1 * 32 + lane];
        float2 v2 = V2[(size_t)k2 * 32 + lane];
        float2 v3 = V2[(size_t)k3 * 32 + lane];
        y.x += p0 * v0.x + p1 * v1.x + p2 * v2.x + p3 * v3.x;
        y.y += p0 * v0.y + p1 * v1.y + p2 * v2.y + p3 * v3.y;
    }
    for (; j < m; j++) {
        int k = sidx[j];
        float p = __uint_as_float(su[k]);
        float2 v = V2[(size_t)k * 32 + lane];
        y.x += p * v.x; y.y += p * v.y;
    }
    int b = bh >> 3, h = bh & 7;
    *reinterpret_cast<float2*>(Y + (size_t)(b * Tc + qi) * Cc + h * HDc + lane * 2) =
        make_float2(y.x * rinv, y.y * rinv);
}

// ---------------------------------------------------------------------------
extern "C" void kernel_launch(void* const* d_in, const int* in_sizes, int n_in,
                              void* d_out, int out_size)
{
    const float* q  = (const float*)d_in[0];
    const float* Wq = (const float*)d_in[2];
    const float* bq = (const float*)d_in[3];
    const float* Wk = (const float*)d_in[4];
    const float* bk = (const float*)d_in[5];
    const float* Wv = (const float*)d_in[6];
    const float* bv = (const float*)d_in[7];
    const float* Wp = (const float*)d_in[8];
    const float* bp = (const float*)d_in[9];

    float *Qh, *Kh, *Vh, *Yb;
    cudaGetSymbolAddress((void**)&Qh, g_Qh);
    cudaGetSymbolAddress((void**)&Kh, g_Kh);
    cudaGetSymbolAddress((void**)&Vh, g_Vh);
    cudaGetSymbolAddress((void**)&Yb, g_Y);

    cudaFuncSetAttribute(attn_kernel, cudaFuncAttributeMaxDynamicSharedMemorySize,
                         (int)sizeof(AttnSmem));

    qkv_kernel<<<dim3(Cc / 128, Mr / 128, 3), 256>>>(q, Wq, bq, Wk, bk, Wv, bv, Qh, Kh, Vh);
    attn_kernel<<<dim3(Tc / QT, BHc), 256, sizeof(AttnSmem)>>>(Qh, Kh, Vh, Yb);
    sgemm_kernel<<<dim3(Cc / 128, Mr / 128), 256>>>(Yb, Wp, bp, (float*)d_out);
}